// round 7
// baseline (speedup 1.0000x reference)
#include <cuda_runtime.h>
#include <cstdint>

// CARAFE: N=4, C=256, H=W=64, K=5, G=1, S=2  ->  out [4,256,128,128] f32
#define KK   5
#define N_   4
#define C_   256
#define H_   64
#define W_   64
#define HO   128
#define WO   128

#define TC   4              // cells per tile (each dim)
#define PRW  8              // patch rows/cols = TC + 4
#define RS2  9              // patch row stride in float2 units (odd -> staggered banks)
#define PAIRSZ 144          // floats per channel-pair patch (8 * 18)
#define STAGEF 576          // floats per 8-channel stage (4 pairs)
#define NBUF 3
#define NTH  32             // one warp per CTA
#define NCHUNK 4
#define CHPC (C_ / NCHUNK)  // 64 channels per CTA
#define NSTAGE (CHPC / 8)   // 8 stages

typedef unsigned long long ull;

__device__ __forceinline__ ull pack2(float lo, float hi) {
    ull r;
    asm("mov.b64 %0, {%1, %2};" : "=l"(r) : "f"(lo), "f"(hi));
    return r;
}
__device__ __forceinline__ void unpack2(float& lo, float& hi, ull v) {
    asm("mov.b64 {%0, %1}, %2;" : "=f"(lo), "=f"(hi) : "l"(v));
}
__device__ __forceinline__ void ffma2(ull& d, ull a, ull b) {
    asm("fma.rn.f32x2 %0, %1, %2, %0;" : "+l"(d) : "l"(a), "l"(b));
}
__device__ __forceinline__ void cpasync4(unsigned saddr, const float* gaddr, unsigned sz) {
    asm volatile("cp.async.ca.shared.global [%0], [%1], 4, %2;"
                 :: "r"(saddr), "l"(gaddr), "r"(sz));
}

__global__ void __launch_bounds__(NTH, 8)
carafe_kernel(const float* __restrict__ feat, const float* __restrict__ masks,
              float* __restrict__ out)
{
    __shared__ __align__(16) float sbuf[NBUF][STAGEF];   // 6912 B

    const int t   = threadIdx.x;
    const int cid = t >> 1;           // 0..15 : cell in 4x4 tile
    const int p   = t & 1;            // output sub-row within cell
    const int hh  = cid >> 2;         // 0..3
    const int ww  = cid & 3;          // 0..3

    const int b     = blockIdx.x;     // 0..4095
    const int chunk = b & 3;
    const int n     = (b >> 2) & 3;
    const int tile  = b >> 4;         // 0..255
    const int tr    = tile >> 4;      // 0..15
    const int tc    = tile & 15;      // 0..15
    const int h0    = tr * TC;
    const int w0    = tc * TC;
    const int oh    = (h0 + hh) * 2 + p;
    const int ow0   = (w0 + ww) * 2;

    // ---- per-thread masks: 25 taps, q-pair ----
    float2 m[25];
    {
        const float* mb = masks + (size_t)n * 25 * (HO * WO) + (size_t)oh * WO + ow0;
        #pragma unroll
        for (int k = 0; k < 25; ++k)
            m[k] = __ldg((const float2*)(mb + (size_t)k * (HO * WO)));
    }

    // ---- loader role: lch = t>>2 (channel 0..7 of stage), rows {t&3, (t&3)+4} ----
    const int lch = t >> 2;
    const int lrb = t & 3;
    const float* fbase = feat + (size_t)n * (C_ * H_ * W_)
                              + (size_t)chunk * CHPC * (H_ * W_)
                              + (size_t)lch * (H_ * W_);
    const int gr0 = h0 - 2 + lrb;     // row for half 0 (half 1 = +4)
    const int gc0 = w0 - 2;
    // validity bitmask: bit (i*8+j) = element (row gr0+4i, col gc0+j) in-bounds
    unsigned msk = 0;
    #pragma unroll
    for (int i = 0; i < 2; ++i) {
        const int gr = gr0 + 4 * i;
        const bool rok = (unsigned)gr < (unsigned)H_;
        #pragma unroll
        for (int j = 0; j < 8; ++j)
            if (rok && (unsigned)(gc0 + j) < (unsigned)W_)
                msk |= 1u << (i * 8 + j);
    }
    const int goff0 = gr0 * W_ + gc0;           // gmem offset, half 0
    const int soff0 = (lch >> 1) * PAIRSZ + lrb * (RS2 * 2) + (lch & 1);  // smem float idx
    const unsigned sA = (unsigned)__cvta_generic_to_shared(&sbuf[0][0]);

    // issue one stage's 16 cp.asyncs into buffer `buf`
    auto issue = [&](int s, int buf) {
        const float* gst = fbase + (size_t)s * 8 * (H_ * W_);
        const unsigned sb0 = sA + (unsigned)(buf * STAGEF + soff0) * 4u;
        #pragma unroll
        for (int i = 0; i < 2; ++i) {
            const float* g = gst + goff0 + i * (4 * W_);
            const unsigned sb = sb0 + i * (4 * RS2 * 2 * 4);
            #pragma unroll
            for (int j = 0; j < 8; ++j) {
                const unsigned sz = (msk >> (i * 8 + j)) & 1u ? 4u : 0u;
                cpasync4(sb + j * 8u, g + j, sz);
            }
        }
        asm volatile("cp.async.commit_group;");
    };

    issue(0, 0);
    issue(1, 1);

    float* obase = out + ((size_t)n * C_ + (size_t)chunk * CHPC) * (HO * WO)
                       + (size_t)oh * WO + ow0;
    const float* cbase0 = &sbuf[0][0] + (hh * RS2 + ww) * 2;

    int buf = 0;
    for (int s = 0; s < NSTAGE; ++s) {
        if (s < NSTAGE - 1) asm volatile("cp.async.wait_group 1;");
        else                asm volatile("cp.async.wait_group 0;");
        __syncwarp();

        // prefetch stage s+2 into the buffer freed by stage s-1
        if (s + 2 < NSTAGE) {
            int nb = buf + 2; if (nb >= NBUF) nb -= NBUF;
            issue(s + 2, nb);
        }

        // compute: 4 channel pairs x q-pair, 25 taps (4 LDS.64 + 2 dups + 8 FFMA2 / tap)
        const float* sb = cbase0 + buf * STAGEF;
        ull a0q0 = 0, a0q1 = 0, a1q0 = 0, a1q1 = 0;
        ull a2q0 = 0, a2q1 = 0, a3q0 = 0, a3q1 = 0;
        #pragma unroll
        for (int ki = 0; ki < KK; ++ki) {
            #pragma unroll
            for (int kj = 0; kj < KK; ++kj) {
                const int k   = ki * KK + kj;
                const int off = (ki * RS2 + kj) * 2;
                const ull f0 = *(const ull*)(sb + 0 * PAIRSZ + off);
                const ull f1 = *(const ull*)(sb + 1 * PAIRSZ + off);
                const ull f2 = *(const ull*)(sb + 2 * PAIRSZ + off);
                const ull f3 = *(const ull*)(sb + 3 * PAIRSZ + off);
                const ull dq0 = pack2(m[k].x, m[k].x);
                const ull dq1 = pack2(m[k].y, m[k].y);
                ffma2(a0q0, f0, dq0);  ffma2(a0q1, f0, dq1);
                ffma2(a1q0, f1, dq0);  ffma2(a1q1, f1, dq1);
                ffma2(a2q0, f2, dq0);  ffma2(a2q1, f2, dq1);
                ffma2(a3q0, f3, dq0);  ffma2(a3q1, f3, dq1);
            }
        }

        // stores: 8 channels x q-pair, STG.64
        {
            const int c0 = s * 8;
            float e0, o0, e1, o1;
            unpack2(e0, o0, a0q0); unpack2(e1, o1, a0q1);
            *(ull*)(obase + (size_t)(c0 + 0) * (HO * WO)) = pack2(e0, e1);
            *(ull*)(obase + (size_t)(c0 + 1) * (HO * WO)) = pack2(o0, o1);
            unpack2(e0, o0, a1q0); unpack2(e1, o1, a1q1);
            *(ull*)(obase + (size_t)(c0 + 2) * (HO * WO)) = pack2(e0, e1);
            *(ull*)(obase + (size_t)(c0 + 3) * (HO * WO)) = pack2(o0, o1);
            unpack2(e0, o0, a2q0); unpack2(e1, o1, a2q1);
            *(ull*)(obase + (size_t)(c0 + 4) * (HO * WO)) = pack2(e0, e1);
            *(ull*)(obase + (size_t)(c0 + 5) * (HO * WO)) = pack2(o0, o1);
            unpack2(e0, o0, a3q0); unpack2(e1, o1, a3q1);
            *(ull*)(obase + (size_t)(c0 + 6) * (HO * WO)) = pack2(e0, e1);
            *(ull*)(obase + (size_t)(c0 + 7) * (HO * WO)) = pack2(o0, o1);
        }

        __syncwarp();   // all lanes done reading buf before it can be re-filled next iters
        if (++buf >= NBUF) buf -= NBUF;
    }
}

extern "C" void kernel_launch(void* const* d_in, const int* in_sizes, int n_in,
                              void* d_out, int out_size) {
    const float* feat  = (const float*)d_in[0];
    const float* masks = (const float*)d_in[1];
    if (n_in >= 2 && in_sizes[0] == N_ * KK * KK * HO * WO &&
        in_sizes[1] == N_ * C_ * H_ * W_) {
        const float* tmp = feat; feat = masks; masks = tmp;
    }
    carafe_kernel<<<256 * N_ * NCHUNK, NTH>>>(feat, masks, (float*)d_out);
}

// round 8
// speedup vs baseline: 1.4300x; 1.4300x over previous
#include <cuda_runtime.h>
#include <cstdint>

// CARAFE: N=4, C=256, H=W=64, K=5, G=1, S=2  ->  out [4,256,128,128] f32
#define KK   5
#define N_   4
#define C_   256
#define H_   64
#define W_   64
#define HO   128
#define WO   128

#define TH_CELLS 4         // input cells per CTA (rows)
#define TW_CELLS 8         // input cells per CTA (cols)
#define PR 8               // patch rows = TH_CELLS + 4
#define PC 12              // patch cols = TW_CELLS + 4
#define PS 13              // row stride in float2 units (odd stagger)
#define PAIR_F (PR * PS * 2)      // 208 floats per channel-pair patch
#define STAGE_F (4 * PAIR_F)      // 832 floats per 8-channel stage
#define NTHREADS 256
#define NSTAGE 32                 // all 256 channels: masks loaded ONCE per thread
#define NLOAD (8 * PR * PC)       // 768 feature elements per stage
#define LPT (NLOAD / NTHREADS)    // 3

typedef unsigned long long ull;

__device__ __forceinline__ ull pack2(float lo, float hi) {
    ull r;
    asm("mov.b64 %0, {%1, %2};" : "=l"(r) : "f"(lo), "f"(hi));
    return r;
}
__device__ __forceinline__ void unpack2(float& lo, float& hi, ull v) {
    asm("mov.b64 {%0, %1}, %2;" : "=f"(lo), "=f"(hi) : "l"(v));
}
__device__ __forceinline__ void ffma2(ull& d, ull a, ull b) {
    asm("fma.rn.f32x2 %0, %1, %2, %0;" : "+l"(d) : "l"(a), "l"(b));
}

__global__ void __launch_bounds__(NTHREADS, 3)
carafe_kernel(const float* __restrict__ feat, const float* __restrict__ masks,
              float* __restrict__ out)
{
    __shared__ __align__(16) float sbuf[2][STAGE_F];   // 6656 B

    const int t    = threadIdx.x;
    const int slot = t >> 7;          // 0/1 : channel-pair slot (uniform per warp)
    const int r    = t & 127;
    const int oh_l = r >> 4;          // 0..7  local output row
    const int ow_l = r & 15;          // 0..15 local output col
    const int hh   = oh_l >> 1;       // input cell row 0..3
    const int wwq  = ow_l >> 1;       // input cell col 0..7

    const int b    = blockIdx.x;      // 0..511
    const int n    = b >> 7;
    const int tidx = b & 127;
    const int th   = tidx >> 3;       // 0..15
    const int tw   = tidx & 7;        // 0..7
    const int h0   = th * TH_CELLS;
    const int w0   = tw * TW_CELLS;
    const int oh   = th * (2 * TH_CELLS) + oh_l;
    const int ow   = tw * (2 * TW_CELLS) + ow_l;

    // ---- per-thread masks (one output pixel), duplicated for channel-packed FFMA2 ----
    ull m[25];
    {
        const float* mb = masks + (size_t)n * 25 * (HO * WO) + (size_t)oh * WO + ow;
        #pragma unroll
        for (int k = 0; k < 25; ++k) {
            const float mv = __ldg(mb + (size_t)k * (HO * WO));
            m[k] = pack2(mv, mv);
        }
    }

    // ---- cooperative-load slots: interleaved (ch&1) channel-pair layout ----
    const float* fbase = feat + (size_t)n * (C_ * H_ * W_);
    int sofs[LPT], gofs[LPT];
    #pragma unroll
    for (int i = 0; i < LPT; ++i) {
        const int e   = t + i * NTHREADS;          // < 768
        const int ch  = e / (PR * PC);
        const int rem = e - ch * (PR * PC);
        const int rr  = rem / PC;
        const int col = rem - rr * PC;
        const int gr  = h0 - 2 + rr;
        const int gc  = w0 - 2 + col;
        sofs[i] = (ch >> 1) * PAIR_F + rr * (PS * 2) + col * 2 + (ch & 1);
        gofs[i] = ((unsigned)gr < (unsigned)H_ && (unsigned)gc < (unsigned)W_)
                      ? (ch * (H_ * W_) + gr * W_ + gc)
                      : -1;
    }

    float v[LPT];

    // prologue: stage 0 -> buffer 0
    #pragma unroll
    for (int i = 0; i < LPT; ++i)
        v[i] = (gofs[i] >= 0) ? __ldg(fbase + gofs[i]) : 0.f;
    #pragma unroll
    for (int i = 0; i < LPT; ++i)
        sbuf[0][sofs[i]] = v[i];
    __syncthreads();

    float* obase = out + (size_t)n * (C_ * HO * WO) + (size_t)oh * WO + ow;

    #pragma unroll 1
    for (int s = 0; s < NSTAGE; ++s) {
        // prefetch next stage's features (latency hidden under compute)
        if (s + 1 < NSTAGE) {
            const float* fb = fbase + (size_t)(s + 1) * 8 * (H_ * W_);
            #pragma unroll
            for (int i = 0; i < LPT; ++i)
                v[i] = (gofs[i] >= 0) ? __ldg(fb + gofs[i]) : 0.f;
        }

        // compute: 2 channel pairs x 25 taps, LDS.64 + FFMA2 each
        const float* sb = &sbuf[s & 1][0] + slot * (2 * PAIR_F)
                          + hh * (PS * 2) + wwq * 2;
        ull a0 = 0, a1 = 0;
        #pragma unroll
        for (int ki = 0; ki < KK; ++ki) {
            #pragma unroll
            for (int kj = 0; kj < KK; ++kj) {
                const int k   = ki * KK + kj;
                const int off = ki * (PS * 2) + kj * 2;
                const ull f0 = *(const ull*)(sb + 0 * PAIR_F + off);
                const ull f1 = *(const ull*)(sb + 1 * PAIR_F + off);
                ffma2(a0, f0, m[k]);
                ffma2(a1, f1, m[k]);
            }
        }

        // stores: 4 channels, channel-strided (coalesced across the warp)
        {
            const int c0 = s * 8 + slot * 4;
            float lo, hi;
            unpack2(lo, hi, a0);
            obase[(size_t)(c0 + 0) * (HO * WO)] = lo;
            obase[(size_t)(c0 + 1) * (HO * WO)] = hi;
            unpack2(lo, hi, a1);
            obase[(size_t)(c0 + 2) * (HO * WO)] = lo;
            obase[(size_t)(c0 + 3) * (HO * WO)] = hi;
        }

        // commit prefetched data to the other buffer
        if (s + 1 < NSTAGE) {
            float* dst = &sbuf[(s + 1) & 1][0];
            #pragma unroll
            for (int i = 0; i < LPT; ++i)
                dst[sofs[i]] = v[i];
        }
        __syncthreads();
    }
}

extern "C" void kernel_launch(void* const* d_in, const int* in_sizes, int n_in,
                              void* d_out, int out_size) {
    const float* feat  = (const float*)d_in[0];
    const float* masks = (const float*)d_in[1];
    if (n_in >= 2 && in_sizes[0] == N_ * KK * KK * HO * WO &&
        in_sizes[1] == N_ * C_ * H_ * W_) {
        const float* tmp = feat; feat = masks; masks = tmp;
    }
    carafe_kernel<<<N_ * 128, NTHREADS>>>(feat, masks, (float*)d_out);
}